// round 13
// baseline (speedup 1.0000x reference)
#include <cuda_runtime.h>
#include <cuda_fp16.h>
#include <cstdint>

#define NN 50000
#define EE 100000
#define NN_PAD 50048
#define KH 576             /* node K layout in halfs: 512 x + 10 PE + 54 zero pad */

#define BM 128
#define BN 128
#define BKH 64             /* k-tile in halfs (4 x k16 mma steps) */
#define RSH 72             /* row stride halfs (64 + 8 pad, conflict-free ldmatrix) */
#define A_HALFS (BM * RSH)
#define STAGE_H ((BM + BN) * RSH)       /* 18432 halfs = 36864 B */
#define SMEM_DYN (3 * STAGE_H * 2)      /* 110592 B -> 2 CTAs/SM */
#define NTHR 128

// ---------------- scratch (device globals; no runtime allocations) ----------
__device__ __half g_G[(size_t)NN_PAD * 1024];   // fp16: [n][0:512]=src-proj, [512:1024]=dst
__device__ __half g_Xp[(size_t)NN_PAD * KH];    // prepared node features, fp16
__device__ __half g_WnodeT[1024 * KH];          // [out j][k], fp16
__device__ __half g_WqaT[512 * 1024];           // [out j][k], fp16
__device__ float  g_p[NN * 10];                 // PE sums; zero at entry
__device__ float  g_deg_in[NN];                 // zero at entry (re-zeroed by edge tail)
__device__ float  g_deg_out[NN];

// ---------------- helpers ---------------------------------------------------
__device__ __forceinline__ uint32_t smem_u32(const void* p) {
    return (uint32_t)__cvta_generic_to_shared(p);
}
__device__ __forceinline__ void cp16(void* sdst, const void* gsrc, int bytes) {
    unsigned d = (unsigned)__cvta_generic_to_shared(sdst);
    asm volatile("cp.async.cg.shared.global [%0], [%1], 16, %2;"
                 :: "r"(d), "l"(gsrc), "r"(bytes));
}
__device__ __forceinline__ void cp_commit() {
    asm volatile("cp.async.commit_group;" ::: "memory");
}

__device__ __forceinline__ void mma_f16(float* c, const uint32_t* a, const uint32_t* b) {
    asm volatile(
        "mma.sync.aligned.m16n8k16.row.col.f32.f16.f16.f32 "
        "{%0,%1,%2,%3}, {%4,%5,%6,%7}, {%8,%9}, {%0,%1,%2,%3};\n"
        : "+f"(c[0]), "+f"(c[1]), "+f"(c[2]), "+f"(c[3])
        : "r"(a[0]), "r"(a[1]), "r"(a[2]), "r"(a[3]), "r"(b[0]), "r"(b[1]));
}

#define LDSM4(d0, d1, d2, d3, addr) \
    asm volatile("ldmatrix.sync.aligned.m8n8.x4.shared.b16 {%0,%1,%2,%3}, [%4];" \
                 : "=r"(d0), "=r"(d1), "=r"(d2), "=r"(d3) : "r"(addr))

// ---------------- combo1: weight pack + out=b2 + conv1 -----------------------
// W1 row map: q:0..511 | src.x:512..1023 | src.pe:1024..1033 | attr:1034..1545
//             dst.x:1546..2057 | dst.pe:2058..2067
#define WTOT (1024 * KH + 512 * 1024)
__global__ void combo1(const float* __restrict__ W1, const float* __restrict__ topic,
                       const float* __restrict__ b2, float* __restrict__ out,
                       const int* __restrict__ srcI, const int* __restrict__ dstI) {
    int idx = blockIdx.x * 256 + threadIdx.x;
    if (idx < 1024 * KH) {
        int j = idx / KH, k = idx % KH;
        bool hi = (j >= 512); int jj = j & 511;
        float v = 0.f;
        if (k < 512)      v = W1[(size_t)((hi ? 1546 : 512) + k) * 512 + jj];
        else if (k < 522) v = W1[(size_t)((hi ? 2058 : 1024) + (k - 512)) * 512 + jj];
        g_WnodeT[idx] = __float2half_rn(v);
    } else if (idx < WTOT) {
        int i2 = idx - 1024 * KH;
        int j = i2 >> 10, k = i2 & 1023;
        int row = (k < 512) ? k : (1034 + (k - 512));
        g_WqaT[i2] = __float2half_rn(W1[(size_t)row * 512 + j]);
    }
    if (idx < EE) {
        out[idx] = b2[0];
        int s = srcI[idx], d = dstI[idx];
        atomicAdd(&g_p[d * 10 + 2], topic[s * 2 + 0]);
        atomicAdd(&g_p[d * 10 + 3], topic[s * 2 + 1]);
        atomicAdd(&g_p[s * 10 + 6], topic[d * 2 + 0]);
        atomicAdd(&g_p[s * 10 + 7], topic[d * 2 + 1]);
        atomicAdd(&g_deg_in[d], 1.f);
        atomicAdd(&g_deg_out[s], 1.f);
    }
}

// round-2 PE sums with round-1 normalization folded in
__global__ void conv2(const int* __restrict__ srcI, const int* __restrict__ dstI) {
    int e = blockIdx.x * 256 + threadIdx.x;
    if (e >= EE) return;
    int s = srcI[e], d = dstI[e];
    float inv_s = 1.f / fmaxf(g_deg_in[s], 1.f);
    float inv_d = 1.f / fmaxf(g_deg_out[d], 1.f);
    atomicAdd(&g_p[d * 10 + 4], g_p[s * 10 + 2] * inv_s);
    atomicAdd(&g_p[d * 10 + 5], g_p[s * 10 + 3] * inv_s);
    atomicAdd(&g_p[s * 10 + 8], g_p[d * 10 + 6] * inv_d);
    atomicAdd(&g_p[s * 10 + 9], g_p[d * 10 + 7] * inv_d);
}

// node features: x' (zero-row -> ne) | topic | normalized PE | zero pad, fp16
__global__ void prep_xp(const float* __restrict__ x, const float* __restrict__ ne,
                        const float* __restrict__ topic) {
    int n = (blockIdx.x * 256 + threadIdx.x) >> 5;
    int lane = threadIdx.x & 31;
    if (n >= NN) return;
    const float4* xr = (const float4*)(x + (size_t)n * 512);
    float4 v[4];
    bool nz = false;
    #pragma unroll
    for (int i = 0; i < 4; ++i) {
        v[i] = xr[i * 32 + lane];
        nz |= (v[i].x != 0.f) | (v[i].y != 0.f) | (v[i].z != 0.f) | (v[i].w != 0.f);
    }
    nz = __any_sync(0xffffffffu, nz);
    __half* dst = g_Xp + (size_t)n * KH;
    const float4* nr = (const float4*)ne;
    #pragma unroll
    for (int i = 0; i < 4; ++i) {
        float4 w = nz ? v[i] : nr[i * 32 + lane];
        __half2 h0 = __floats2half2_rn(w.x, w.y);
        __half2 h1 = __floats2half2_rn(w.z, w.w);
        uint2 u;
        u.x = *(uint32_t*)&h0; u.y = *(uint32_t*)&h1;
        *(uint2*)(dst + (i * 32 + lane) * 4) = u;
    }
    float val = 0.f;
    if (lane < 2) {
        val = topic[n * 2 + lane];
    } else if (lane < 10) {
        float di = fmaxf(g_deg_in[n], 1.f);
        float dv = fmaxf(g_deg_out[n], 1.f);
        val = g_p[n * 10 + lane];
        if (lane < 6) val /= di;
        else          val /= dv;
    }
    dst[512 + lane] = __float2half_rn(val);   // real data ends at col 521
    dst[544 + lane] = __half(0.f);            // pad 544..575
}

// ---------------- GEMM core shared pieces ------------------------------------
extern __shared__ char dynraw[];

// warp tile 64x64: wm = warp&1 (m half), wn = warp>>1 in {0,1} (n half)
#define LOAD_FRAGS(ks)                                                           \
    do {                                                                         \
        _Pragma("unroll")                                                        \
        for (int mf = 0; mf < 4; ++mf) {                                         \
            uint32_t ad = Abase + (uint32_t)(((wm * 64 + mf * 16) * RSH          \
                                              + (ks) * 16) * 2) + laneoff;       \
            LDSM4(a[mf][0], a[mf][1], a[mf][2], a[mf][3], ad);                   \
        }                                                                        \
        _Pragma("unroll")                                                        \
        for (int h = 0; h < 4; ++h) {                                            \
            uint32_t q0, q1, q2, q3;                                             \
            uint32_t bd = Bbase + (uint32_t)(((wn * 64 + h * 16) * RSH           \
                                              + (ks) * 16) * 2) + laneoff;       \
            LDSM4(q0, q1, q2, q3, bd);                                           \
            b[2 * h][0] = q0; b[2 * h + 1][0] = q1;                              \
            b[2 * h][1] = q2; b[2 * h + 1][1] = q3;                              \
        }                                                                        \
    } while (0)

#define MMA_ALL()                                                                \
    do {                                                                         \
        _Pragma("unroll")                                                        \
        for (int mf = 0; mf < 4; ++mf)                                           \
            _Pragma("unroll")                                                    \
            for (int nf = 0; nf < 8; ++nf)                                       \
                mma_f16(acc[mf][nf], a[mf], b[nf]);                              \
    } while (0)

// ---------------- node GEMM: g_G = g_Xp @ g_WnodeT^T (3-stage, 2 CTAs/SM) ----
__global__ __launch_bounds__(NTHR, 2) void node_gemm() {
    __half* dynsmem = (__half*)dynraw;
    const int tid = threadIdx.x, warp = tid >> 5, lane = tid & 31;
    const int wm = warp & 1, wn = warp >> 1;
    const int g = lane >> 2, t = lane & 3;
    const int n0 = blockIdx.x * BN, m0 = blockIdx.y * BM;
    const int KT = KH / BKH;  // 9 (last tile: real data only in first k16 step)
    const uint32_t laneoff = (uint32_t)(((lane & 15) * RSH + (lane >> 4) * 8) * 2);

    float acc[4][8][4];
    #pragma unroll
    for (int i = 0; i < 4; ++i)
        #pragma unroll
        for (int j = 0; j < 8; ++j)
            #pragma unroll
            for (int k = 0; k < 4; ++k) acc[i][j][k] = 0.f;

    auto load_tile = [&](int stage, int kt) {
        __half* As = dynsmem + stage * STAGE_H;
        __half* Bs = As + A_HALFS;
        int kb = kt * BKH;
        #pragma unroll
        for (int i = 0; i < 8; ++i) {
            int id = i * NTHR + tid;
            int row = id >> 3, ch = id & 7;
            int n = m0 + row;
            cp16(As + row * RSH + ch * 8,
                 g_Xp + (size_t)n * KH + kb + ch * 8, (n < NN) ? 16 : 0);
        }
        #pragma unroll
        for (int i = 0; i < 8; ++i) {
            int id = i * NTHR + tid;
            int row = id >> 3, ch = id & 7;
            cp16(Bs + row * RSH + ch * 8,
                 g_WnodeT + (size_t)(n0 + row) * KH + kb + ch * 8, 16);
        }
        cp_commit();
    };

    load_tile(0, 0);
    load_tile(1, 1);

    for (int kt = 0; kt < KT; ++kt) {
        if (kt + 1 < KT) asm volatile("cp.async.wait_group 1;" ::: "memory");
        else             asm volatile("cp.async.wait_group 0;" ::: "memory");
        __syncthreads();

        if (kt + 2 < KT) load_tile((kt + 2) % 3, kt + 2);

        const __half* stg = dynsmem + (kt % 3) * STAGE_H;
        const uint32_t Abase = smem_u32(stg);
        const uint32_t Bbase = smem_u32(stg + A_HALFS);
        uint32_t a[4][4], b[8][2];
        const int nks = (kt == KT - 1) ? 1 : 4;  // cols 528..575 all zero
        #pragma unroll
        for (int ks = 0; ks < 4; ++ks) {
            if (ks >= nks) break;
            LOAD_FRAGS(ks);
            MMA_ALL();
        }
    }

    #pragma unroll
    for (int mf = 0; mf < 4; ++mf) {
        #pragma unroll
        for (int half = 0; half < 2; ++half) {
            int r = wm * 64 + mf * 16 + g + half * 8;
            int n = m0 + r;
            if (n < NN) {
                __half* Gp = g_G + (size_t)n * 1024 + n0;
                #pragma unroll
                for (int nf = 0; nf < 8; ++nf) {
                    int cj = wn * 64 + nf * 8 + 2 * t;
                    __half2 hv = __floats2half2_rn(acc[mf][nf][half * 2 + 0],
                                                   acc[mf][nf][half * 2 + 1]);
                    *(__half2*)(Gp + cj) = hv;
                }
            }
        }
    }
}

// ---------------- edge GEMM (A: fp32 LDG -> fp16 STS) + fused epilogue -------
__global__ __launch_bounds__(NTHR, 2) void edge_gemm(
    const float* __restrict__ q_emb, const float* __restrict__ edge_attr,
    const int* __restrict__ srcI, const int* __restrict__ dstI,
    const float* __restrict__ b1, const float* __restrict__ W2,
    float* __restrict__ out)
{
    __half* dynsmem = (__half*)dynraw;
    __shared__ float sB1[BN];
    __shared__ float sW2[BN];

    const int tid = threadIdx.x, warp = tid >> 5, lane = tid & 31;
    const int wm = warp & 1, wn = warp >> 1;
    const int g = lane >> 2, t = lane & 3;
    const int n0 = blockIdx.x * BN, m0 = blockIdx.y * BM;
    const int KT = 1024 / BKH;  // 16
    const uint32_t laneoff = (uint32_t)(((lane & 15) * RSH + (lane >> 4) * 8) * 2);

    sB1[tid] = b1[n0 + tid];
    sW2[tid] = W2[n0 + tid];

    // A staging: thread owns row = tid, all 64 fp32 cols of each tile
    const int arow = tid;
    const int ae = m0 + arow;
    const bool aval = (ae < EE);

    uint32_t rAh[32];  // 64 halfs, converted at LDG time
    auto ldgA = [&](int kt) {
        int kg = kt * 64;  // tile fully inside q (kg<512) or attr
        const float* src = (kg < 512) ? q_emb + (size_t)ae * 512 + kg
                                      : edge_attr + (size_t)ae * 512 + (kg - 512);
        #pragma unroll
        for (int i = 0; i < 16; ++i) {
            float4 v = aval ? *(const float4*)(src + i * 4)
                            : make_float4(0.f, 0.f, 0.f, 0.f);
            __half2 h0 = __floats2half2_rn(v.x, v.y);
            __half2 h1 = __floats2half2_rn(v.z, v.w);
            rAh[2 * i + 0] = *(uint32_t*)&h0;
            rAh[2 * i + 1] = *(uint32_t*)&h1;
        }
    };
    auto stsA = [&](int stage) {
        __half* dst = dynsmem + stage * STAGE_H + arow * RSH;
        #pragma unroll
        for (int i = 0; i < 8; ++i) {
            uint4 u;
            u.x = rAh[4 * i + 0]; u.y = rAh[4 * i + 1];
            u.z = rAh[4 * i + 2]; u.w = rAh[4 * i + 3];
            *(uint4*)(dst + i * 8) = u;
        }
    };
    auto loadB = [&](int stage, int kt) {
        __half* Bs = dynsmem + stage * STAGE_H + A_HALFS;
        int kb = kt * BKH;
        #pragma unroll
        for (int i = 0; i < 8; ++i) {
            int id = i * NTHR + tid;
            int row = id >> 3, ch = id & 7;
            cp16(Bs + row * RSH + ch * 8,
                 g_WqaT + (size_t)(n0 + row) * 1024 + kb + ch * 8, 16);
        }
        cp_commit();
    };

    float acc[4][8][4];
    #pragma unroll
    for (int i = 0; i < 4; ++i)
        #pragma unroll
        for (int j = 0; j < 8; ++j)
            #pragma unroll
            for (int k = 0; k < 4; ++k) acc[i][j][k] = 0.f;

    // prologue: A0 staged, A1 in regs; B0, B1 in flight
    ldgA(0); stsA(0);
    ldgA(1);
    loadB(0, 0);
    loadB(1, 1);

    for (int kt = 0; kt < KT; ++kt) {
        if (kt + 1 < KT) asm volatile("cp.async.wait_group 1;" ::: "memory");
        else             asm volatile("cp.async.wait_group 0;" ::: "memory");
        __syncthreads();  // A(kt) STS + B(kt) visible

        if (kt + 2 < KT) loadB((kt + 2) % 3, kt + 2);

        const __half* stg = dynsmem + (kt % 3) * STAGE_H;
        const uint32_t Abase = smem_u32(stg);
        const uint32_t Bbase = smem_u32(stg + A_HALFS);
        uint32_t a[4][4], b[8][2];
        #pragma unroll
        for (int ks = 0; ks < 4; ++ks) {
            LOAD_FRAGS(ks);
            MMA_ALL();
        }

        // stage A(kt+1) into smem; start LDG of A(kt+2)
        if (kt + 1 < KT) {
            stsA((kt + 1) % 3);
            if (kt + 2 < KT) ldgA(kt + 2);
        }
    }

    // epilogue: z = acc + b1 + G_src[s] + G_dst[d]; relu; dot W2; atomic add
    #pragma unroll
    for (int mf = 0; mf < 4; ++mf) {
        #pragma unroll
        for (int half = 0; half < 2; ++half) {
            int r = wm * 64 + mf * 16 + g + half * 8;
            int e = m0 + r;
            float rowsum = 0.f;
            if (e < EE) {
                int s = srcI[e], d = dstI[e];
                const __half* Gs = g_G + (size_t)s * 1024 + n0;
                const __half* Gd = g_G + (size_t)d * 1024 + 512 + n0;
                #pragma unroll
                for (int nf = 0; nf < 8; ++nf) {
                    int cj = wn * 64 + nf * 8 + 2 * t;
                    float2 gs = __half22float2(*(const __half2*)(Gs + cj));
                    float2 gd = __half22float2(*(const __half2*)(Gd + cj));
                    float z0 = acc[mf][nf][half * 2 + 0] + sB1[cj] + gs.x + gd.x;
                    float z1 = acc[mf][nf][half * 2 + 1] + sB1[cj + 1] + gs.y + gd.y;
                    rowsum = fmaf(fmaxf(z0, 0.f), sW2[cj], rowsum);
                    rowsum = fmaf(fmaxf(z1, 0.f), sW2[cj + 1], rowsum);
                }
            }
            rowsum += __shfl_xor_sync(0xffffffffu, rowsum, 1);
            rowsum += __shfl_xor_sync(0xffffffffu, rowsum, 2);
            if (t == 0 && e < EE) atomicAdd(out + e, rowsum);
        }
    }

    // tail: re-zero PE scratch + degrees for the next graph replay
    {
        int gid = blockIdx.y * gridDim.x + blockIdx.x;
        int n = gid * NTHR + tid;
        if (n < NN) {
            float2 z2 = make_float2(0.f, 0.f);
            *(float2*)&g_p[n * 10 + 2] = z2;
            *(float2*)&g_p[n * 10 + 4] = z2;
            *(float2*)&g_p[n * 10 + 6] = z2;
            *(float2*)&g_p[n * 10 + 8] = z2;
            g_deg_in[n] = 0.f;
            g_deg_out[n] = 0.f;
        }
    }
}

// ---------------- launch ------------------------------------------------------
extern "C" void kernel_launch(void* const* d_in, const int* in_sizes, int n_in,
                              void* d_out, int out_size) {
    const float* x     = (const float*)d_in[0];
    const int*   ei    = (const int*)d_in[1];
    const float* attr  = (const float*)d_in[2];
    const float* topic = (const float*)d_in[3];
    const float* qemb  = (const float*)d_in[4];
    const float* ne    = (const float*)d_in[5];
    const float* W1    = (const float*)d_in[6];
    const float* b1    = (const float*)d_in[7];
    const float* W2    = (const float*)d_in[8];
    const float* b2    = (const float*)d_in[9];
    float* out = (float*)d_out;
    const int* srcI = ei;
    const int* dstI = ei + EE;

    cudaFuncSetAttribute(node_gemm, cudaFuncAttributeMaxDynamicSharedMemorySize, SMEM_DYN);
    cudaFuncSetAttribute(edge_gemm, cudaFuncAttributeMaxDynamicSharedMemorySize, SMEM_DYN);

    combo1<<<(WTOT + 255) / 256, 256>>>(W1, topic, b2, out, srcI, dstI);
    conv2<<<(EE + 255) / 256, 256>>>(srcI, dstI);
    prep_xp<<<(NN * 32 + 255) / 256, 256>>>(x, ne, topic);
    // 4th launch -> gets the ncu profile
    node_gemm<<<dim3(1024 / BN, (NN + BM - 1) / BM), NTHR, SMEM_DYN>>>();
    edge_gemm<<<dim3(512 / BN, (EE + BM - 1) / BM), NTHR, SMEM_DYN>>>(
        qemb, attr, srcI, dstI, b1, W2, out);
}

// round 14
// speedup vs baseline: 1.3014x; 1.3014x over previous
#include <cuda_runtime.h>
#include <cuda_fp16.h>
#include <cstdint>

#define NN 50000
#define EE 100000
#define NN_PAD 50048
#define KH 576             /* node K layout in halfs: 512 x + 10 PE + 54 zero pad */

#define BM 128
#define BN 256
#define BKH 64             /* k-tile in halfs (4 x k16 mma steps) */
#define RSH 72             /* row stride halfs (64 + 8 pad, conflict-free ldmatrix) */
#define A_HALFS (BM * RSH)
#define STAGE_H ((BM + BN) * RSH)       /* 27648 halfs = 55296 B */
#define SMEM_NODE (4 * STAGE_H * 2)     /* 221184 B, 4-stage */
#define SMEM_EDGE (3 * STAGE_H * 2)     /* 165888 B, 3-stage */

// ---------------- scratch (device globals; no runtime allocations) ----------
__device__ __half g_G[(size_t)NN_PAD * 1024];   // fp16: [n][0:512]=src-proj, [512:1024]=dst
__device__ __half g_Xp[(size_t)NN_PAD * KH];    // prepared node features, fp16
__device__ __half g_WnodeT[1024 * KH];          // [out j][k], fp16
__device__ __half g_WqaT[512 * 1024];           // [out j][k], fp16
__device__ float  g_p[NN * 10];                 // PE sums; zero at entry
__device__ float  g_deg_in[NN];                 // zero at entry (re-zeroed by edge tail)
__device__ float  g_deg_out[NN];

// ---------------- helpers ---------------------------------------------------
__device__ __forceinline__ uint32_t smem_u32(const void* p) {
    return (uint32_t)__cvta_generic_to_shared(p);
}
__device__ __forceinline__ void cp16(void* sdst, const void* gsrc, int bytes) {
    unsigned d = (unsigned)__cvta_generic_to_shared(sdst);
    asm volatile("cp.async.cg.shared.global [%0], [%1], 16, %2;"
                 :: "r"(d), "l"(gsrc), "r"(bytes));
}
__device__ __forceinline__ void cp_commit() {
    asm volatile("cp.async.commit_group;" ::: "memory");
}

__device__ __forceinline__ void mma_f16(float* c, const uint32_t* a, const uint32_t* b) {
    asm volatile(
        "mma.sync.aligned.m16n8k16.row.col.f32.f16.f16.f32 "
        "{%0,%1,%2,%3}, {%4,%5,%6,%7}, {%8,%9}, {%0,%1,%2,%3};\n"
        : "+f"(c[0]), "+f"(c[1]), "+f"(c[2]), "+f"(c[3])
        : "r"(a[0]), "r"(a[1]), "r"(a[2]), "r"(a[3]), "r"(b[0]), "r"(b[1]));
}

#define LDSM4(d0, d1, d2, d3, addr) \
    asm volatile("ldmatrix.sync.aligned.m8n8.x4.shared.b16 {%0,%1,%2,%3}, [%4];" \
                 : "=r"(d0), "=r"(d1), "=r"(d2), "=r"(d3) : "r"(addr))

// ---------------- prep_a: tiled weight transpose + conv1 + out=b2 ------------
// W1 row map: q:0..511 | src.x:512..1023 | src.pe:1024..1033 | attr:1034..1545
//             dst.x:1546..2057 | dst.pe:2058..2067
// Wnode tiles: 17 k-tiles x 32 j-tiles = 544 blocks
// Wqa tiles:   32 k-tiles x 16 j-tiles = 512 blocks
// conv1/out:   391 blocks of 256 edges
#define NB_WNODE (17 * 32)
#define NB_WQA   (32 * 16)
#define NB_EDGE  ((EE + 255) / 256)
#define NB_PREPA (NB_WNODE + NB_WQA + NB_EDGE)

__global__ void prep_a(const float* __restrict__ W1, const float* __restrict__ topic,
                       const float* __restrict__ b2, float* __restrict__ out,
                       const int* __restrict__ srcI, const int* __restrict__ dstI) {
    __shared__ float tile[32][33];
    int bid = blockIdx.x;
    int tx = threadIdx.x & 31, ty = threadIdx.x >> 5;   // 32 x 8

    if (bid < NB_WNODE) {
        int kb = (bid % 17) * 32, jb = (bid / 17) * 32;
        #pragma unroll
        for (int i = 0; i < 4; ++i) {
            int k = kb + ty + i * 8;
            int j = jb + tx;
            bool hi = (j >= 512); int jj = j & 511;
            float v = 0.f;
            if (k < 512)      v = W1[(size_t)((hi ? 1546 : 512) + k) * 512 + jj];
            else if (k < 522) v = W1[(size_t)((hi ? 2058 : 1024) + (k - 512)) * 512 + jj];
            tile[ty + i * 8][tx] = v;
        }
        __syncthreads();
        #pragma unroll
        for (int i = 0; i < 4; ++i) {
            int j = jb + ty + i * 8;
            int k = kb + tx;
            g_WnodeT[(size_t)j * KH + k] = __float2half_rn(tile[tx][ty + i * 8]);
        }
        // cover the KH pad (k 544..575) once per j-tile using the kb==512 tile
        if (kb == 544 - 32) {
            #pragma unroll
            for (int i = 0; i < 4; ++i) {
                int j = jb + ty + i * 8;
                g_WnodeT[(size_t)j * KH + 544 + tx] = __half(0.f);
            }
        }
    } else if (bid < NB_WNODE + NB_WQA) {
        int b2i = bid - NB_WNODE;
        int kb = (b2i % 32) * 32, jb = (b2i / 32) * 32;
        #pragma unroll
        for (int i = 0; i < 4; ++i) {
            int k = kb + ty + i * 8;
            int row = (k < 512) ? k : (1034 + (k - 512));
            tile[ty + i * 8][tx] = W1[(size_t)row * 512 + jb + tx];
        }
        __syncthreads();
        #pragma unroll
        for (int i = 0; i < 4; ++i) {
            int j = jb + ty + i * 8;
            int k = kb + tx;
            g_WqaT[(size_t)j * 1024 + k] = __float2half_rn(tile[tx][ty + i * 8]);
        }
    } else {
        int e = (bid - NB_WNODE - NB_WQA) * 256 + threadIdx.x;
        if (e < EE) {
            out[e] = b2[0];
            int s = srcI[e], d = dstI[e];
            atomicAdd(&g_p[d * 10 + 2], topic[s * 2 + 0]);
            atomicAdd(&g_p[d * 10 + 3], topic[s * 2 + 1]);
            atomicAdd(&g_p[s * 10 + 6], topic[d * 2 + 0]);
            atomicAdd(&g_p[s * 10 + 7], topic[d * 2 + 1]);
            atomicAdd(&g_deg_in[d], 1.f);
            atomicAdd(&g_deg_out[s], 1.f);
        }
    }
}

// round-2 PE sums with round-1 normalization folded in
__global__ void conv2(const int* __restrict__ srcI, const int* __restrict__ dstI) {
    int e = blockIdx.x * 256 + threadIdx.x;
    if (e >= EE) return;
    int s = srcI[e], d = dstI[e];
    float inv_s = 1.f / fmaxf(g_deg_in[s], 1.f);
    float inv_d = 1.f / fmaxf(g_deg_out[d], 1.f);
    atomicAdd(&g_p[d * 10 + 4], g_p[s * 10 + 2] * inv_s);
    atomicAdd(&g_p[d * 10 + 5], g_p[s * 10 + 3] * inv_s);
    atomicAdd(&g_p[s * 10 + 8], g_p[d * 10 + 6] * inv_d);
    atomicAdd(&g_p[s * 10 + 9], g_p[d * 10 + 7] * inv_d);
}

// node features: x' (zero-row -> ne) | topic | normalized PE | zero pad, fp16
__global__ void prep_xp(const float* __restrict__ x, const float* __restrict__ ne,
                        const float* __restrict__ topic) {
    int n = (blockIdx.x * 256 + threadIdx.x) >> 5;
    int lane = threadIdx.x & 31;
    if (n >= NN) return;
    const float4* xr = (const float4*)(x + (size_t)n * 512);
    float4 v[4];
    bool nz = false;
    #pragma unroll
    for (int i = 0; i < 4; ++i) {
        v[i] = xr[i * 32 + lane];
        nz |= (v[i].x != 0.f) | (v[i].y != 0.f) | (v[i].z != 0.f) | (v[i].w != 0.f);
    }
    nz = __any_sync(0xffffffffu, nz);
    __half* dst = g_Xp + (size_t)n * KH;
    const float4* nr = (const float4*)ne;
    #pragma unroll
    for (int i = 0; i < 4; ++i) {
        float4 w = nz ? v[i] : nr[i * 32 + lane];
        __half2 h0 = __floats2half2_rn(w.x, w.y);
        __half2 h1 = __floats2half2_rn(w.z, w.w);
        uint2 u;
        u.x = *(uint32_t*)&h0; u.y = *(uint32_t*)&h1;
        *(uint2*)(dst + (i * 32 + lane) * 4) = u;
    }
    float val = 0.f;
    if (lane < 2) {
        val = topic[n * 2 + lane];
    } else if (lane < 10) {
        float di = fmaxf(g_deg_in[n], 1.f);
        float dv = fmaxf(g_deg_out[n], 1.f);
        val = g_p[n * 10 + lane];
        if (lane < 6) val /= di;
        else          val /= dv;
    }
    dst[512 + lane] = __float2half_rn(val);   // real data ends at col 521
    dst[544 + lane] = __half(0.f);            // pad 544..575
}

// ---------------- GEMM core shared pieces ------------------------------------
extern __shared__ char dynraw[];

#define LOAD_FRAGS(ks)                                                           \
    do {                                                                         \
        _Pragma("unroll")                                                        \
        for (int mf = 0; mf < 4; ++mf) {                                         \
            uint32_t ad = Abase + (uint32_t)(((wm * 64 + mf * 16) * RSH          \
                                              + (ks) * 16) * 2) + laneoff;       \
            LDSM4(a[mf][0], a[mf][1], a[mf][2], a[mf][3], ad);                   \
        }                                                                        \
        _Pragma("unroll")                                                        \
        for (int h = 0; h < 4; ++h) {                                            \
            uint32_t q0, q1, q2, q3;                                             \
            uint32_t bd = Bbase + (uint32_t)(((wn * 64 + h * 16) * RSH           \
                                              + (ks) * 16) * 2) + laneoff;       \
            LDSM4(q0, q1, q2, q3, bd);                                           \
            b[2 * h][0] = q0; b[2 * h + 1][0] = q1;                              \
            b[2 * h][1] = q2; b[2 * h + 1][1] = q3;                              \
        }                                                                        \
    } while (0)

#define MMA_ALL()                                                                \
    do {                                                                         \
        _Pragma("unroll")                                                        \
        for (int mf = 0; mf < 4; ++mf)                                           \
            _Pragma("unroll")                                                    \
            for (int nf = 0; nf < 8; ++nf)                                       \
                mma_f16(acc[mf][nf], a[mf], b[nf]);                              \
    } while (0)

// ---------------- node GEMM: g_G = g_Xp @ g_WnodeT^T (4-stage cp.async) ------
__global__ __launch_bounds__(256, 1) void node_gemm() {
    __half* dynsmem = (__half*)dynraw;
    const int tid = threadIdx.x, warp = tid >> 5, lane = tid & 31;
    const int wm = warp & 1, wn = warp >> 1;
    const int g = lane >> 2, t = lane & 3;
    const int n0 = blockIdx.x * BN, m0 = blockIdx.y * BM;
    const int KT = KH / BKH;  // 9 (last tile: real data only in first k16 step)
    const uint32_t laneoff = (uint32_t)(((lane & 15) * RSH + (lane >> 4) * 8) * 2);

    float acc[4][8][4];
    #pragma unroll
    for (int i = 0; i < 4; ++i)
        #pragma unroll
        for (int j = 0; j < 8; ++j)
            #pragma unroll
            for (int k = 0; k < 4; ++k) acc[i][j][k] = 0.f;

    auto load_tile = [&](int stage, int kt) {
        __half* As = dynsmem + stage * STAGE_H;
        __half* Bs = As + A_HALFS;
        int kb = kt * BKH;
        #pragma unroll
        for (int i = 0; i < 4; ++i) {
            int id = i * 256 + tid;
            int row = id >> 3, ch = id & 7;
            int n = m0 + row;
            cp16(As + row * RSH + ch * 8,
                 g_Xp + (size_t)n * KH + kb + ch * 8, (n < NN) ? 16 : 0);
        }
        #pragma unroll
        for (int i = 0; i < 8; ++i) {
            int id = i * 256 + tid;
            int row = id >> 3, ch = id & 7;
            cp16(Bs + row * RSH + ch * 8,
                 g_WnodeT + (size_t)(n0 + row) * KH + kb + ch * 8, 16);
        }
        cp_commit();
    };

    load_tile(0, 0);
    load_tile(1, 1);

    for (int kt = 0; kt < KT; ++kt) {
        if (kt + 2 < KT) load_tile((kt + 2) & 3, kt + 2);
        int rem = KT - 1 - kt;
        if (rem >= 2)      asm volatile("cp.async.wait_group 2;" ::: "memory");
        else if (rem == 1) asm volatile("cp.async.wait_group 1;" ::: "memory");
        else               asm volatile("cp.async.wait_group 0;" ::: "memory");
        __syncthreads();

        const __half* stg = dynsmem + (kt & 3) * STAGE_H;
        const uint32_t Abase = smem_u32(stg);
        const uint32_t Bbase = smem_u32(stg + A_HALFS);
        uint32_t a[4][4], b[8][2];
        const bool last = (kt == KT - 1);
        #pragma unroll
        for (int ks = 0; ks < 4; ++ks) {
            if (last && ks > 0) break;   // cols 528..575 are all zero
            LOAD_FRAGS(ks);
            MMA_ALL();
        }
    }

    #pragma unroll
    for (int mf = 0; mf < 4; ++mf) {
        #pragma unroll
        for (int half = 0; half < 2; ++half) {
            int r = wm * 64 + mf * 16 + g + half * 8;
            int n = m0 + r;
            if (n < NN) {
                __half* Gp = g_G + (size_t)n * 1024 + n0;
                #pragma unroll
                for (int nf = 0; nf < 8; ++nf) {
                    int cj = wn * 64 + nf * 8 + 2 * t;
                    __half2 hv = __floats2half2_rn(acc[mf][nf][half * 2 + 0],
                                                   acc[mf][nf][half * 2 + 1]);
                    *(__half2*)(Gp + cj) = hv;
                }
            }
        }
    }
}

// ---------------- edge GEMM (A: fp32 LDG -> fp16 STS) + fused epilogue -------
__global__ __launch_bounds__(256, 1) void edge_gemm(
    const float* __restrict__ q_emb, const float* __restrict__ edge_attr,
    const int* __restrict__ srcI, const int* __restrict__ dstI,
    const float* __restrict__ b1, const float* __restrict__ W2,
    float* __restrict__ out)
{
    __half* dynsmem = (__half*)dynraw;
    __shared__ float sB1[BN];
    __shared__ float sW2[BN];

    const int tid = threadIdx.x, warp = tid >> 5, lane = tid & 31;
    const int wm = warp & 1, wn = warp >> 1;
    const int g = lane >> 2, t = lane & 3;
    const int n0 = blockIdx.x * BN, m0 = blockIdx.y * BM;
    const int KT = 1024 / BKH;  // 16
    const uint32_t laneoff = (uint32_t)(((lane & 15) * RSH + (lane >> 4) * 8) * 2);

    sB1[tid] = b1[n0 + tid];
    sW2[tid] = W2[n0 + tid];

    // A staging: thread owns row = tid>>1, fp32 cols [(tid&1)*32, +32) of each tile
    const int arow = tid >> 1;
    const int acol = (tid & 1) * 32;
    const int ae = m0 + arow;
    const bool aval = (ae < EE);

    float4 rA[8];
    auto ldgA = [&](int kt) {
        int kg = kt * 64 + acol;
        const float* src = (kg < 512) ? q_emb + (size_t)ae * 512 + kg
                                      : edge_attr + (size_t)ae * 512 + (kg - 512);
        if (aval) {
            #pragma unroll
            for (int i = 0; i < 8; ++i) rA[i] = *(const float4*)(src + i * 4);
        } else {
            #pragma unroll
            for (int i = 0; i < 8; ++i) rA[i] = make_float4(0.f, 0.f, 0.f, 0.f);
        }
    };
    auto stsA = [&](int stage) {
        __half* dst = dynsmem + stage * STAGE_H + arow * RSH + acol;
        #pragma unroll
        for (int i = 0; i < 8; ++i) {
            __half2 h0 = __floats2half2_rn(rA[i].x, rA[i].y);
            __half2 h1 = __floats2half2_rn(rA[i].z, rA[i].w);
            uint2 u;
            u.x = *(uint32_t*)&h0; u.y = *(uint32_t*)&h1;
            *(uint2*)(dst + i * 4) = u;
        }
    };
    auto loadB = [&](int stage, int kt) {
        __half* Bs = dynsmem + stage * STAGE_H + A_HALFS;
        int kb = kt * BKH;
        #pragma unroll
        for (int i = 0; i < 8; ++i) {
            int id = i * 256 + tid;
            int row = id >> 3, ch = id & 7;
            cp16(Bs + row * RSH + ch * 8,
                 g_WqaT + (size_t)(n0 + row) * 1024 + kb + ch * 8, 16);
        }
        cp_commit();
    };

    float acc[4][8][4];
    #pragma unroll
    for (int i = 0; i < 4; ++i)
        #pragma unroll
        for (int j = 0; j < 8; ++j)
            #pragma unroll
            for (int k = 0; k < 4; ++k) acc[i][j][k] = 0.f;

    // prologue: A0 direct, A1 staged in regs; B0, B1 in flight
    ldgA(0); stsA(0);
    ldgA(1);
    loadB(0, 0);
    loadB(1, 1);

    for (int kt = 0; kt < KT; ++kt) {
        if (kt + 1 < KT) asm volatile("cp.async.wait_group 1;" ::: "memory");
        else             asm volatile("cp.async.wait_group 0;" ::: "memory");
        __syncthreads();  // A(kt) STS + B(kt) visible

        if (kt + 2 < KT) loadB((kt + 2) % 3, kt + 2);

        const __half* stg = dynsmem + (kt % 3) * STAGE_H;
        const uint32_t Abase = smem_u32(stg);
        const uint32_t Bbase = smem_u32(stg + A_HALFS);
        uint32_t a[4][4], b[8][2];
        #pragma unroll
        for (int ks = 0; ks < 4; ++ks) {
            LOAD_FRAGS(ks);
            MMA_ALL();
        }

        if (kt + 1 < KT) {
            stsA((kt + 1) % 3);
            if (kt + 2 < KT) ldgA(kt + 2);
        }
    }

    // epilogue: z = acc + b1 + G_src[s] + G_dst[d]; relu; dot W2; atomic add
    #pragma unroll
    for (int mf = 0; mf < 4; ++mf) {
        #pragma unroll
        for (int half = 0; half < 2; ++half) {
            int r = wm * 64 + mf * 16 + g + half * 8;
            int e = m0 + r;
            float rowsum = 0.f;
            if (e < EE) {
                int s = srcI[e], d = dstI[e];
                const __half* Gs = g_G + (size_t)s * 1024 + n0;
                const __half* Gd = g_G + (size_t)d * 1024 + 512 + n0;
                #pragma unroll
                for (int nf = 0; nf < 8; ++nf) {
                    int cj = wn * 64 + nf * 8 + 2 * t;
                    float2 gs = __half22float2(*(const __half2*)(Gs + cj));
                    float2 gd = __half22float2(*(const __half2*)(Gd + cj));
                    float z0 = acc[mf][nf][half * 2 + 0] + sB1[cj] + gs.x + gd.x;
                    float z1 = acc[mf][nf][half * 2 + 1] + sB1[cj + 1] + gs.y + gd.y;
                    rowsum = fmaf(fmaxf(z0, 0.f), sW2[cj], rowsum);
                    rowsum = fmaf(fmaxf(z1, 0.f), sW2[cj + 1], rowsum);
                }
            }
            rowsum += __shfl_xor_sync(0xffffffffu, rowsum, 1);
            rowsum += __shfl_xor_sync(0xffffffffu, rowsum, 2);
            if (t == 0 && e < EE) atomicAdd(out + e, rowsum);
        }
    }

    // tail: re-zero PE scratch + degrees for the next graph replay
    {
        int gid = blockIdx.y * gridDim.x + blockIdx.x;
        int n = gid * 256 + tid;
        if (n < NN) {
            float2 z2 = make_float2(0.f, 0.f);
            *(float2*)&g_p[n * 10 + 2] = z2;
            *(float2*)&g_p[n * 10 + 4] = z2;
            *(float2*)&g_p[n * 10 + 6] = z2;
            *(float2*)&g_p[n * 10 + 8] = z2;
            g_deg_in[n] = 0.f;
            g_deg_out[n] = 0.f;
        }
    }
}

// ---------------- launch ------------------------------------------------------
extern "C" void kernel_launch(void* const* d_in, const int* in_sizes, int n_in,
                              void* d_out, int out_size) {
    const float* x     = (const float*)d_in[0];
    const int*   ei    = (const int*)d_in[1];
    const float* attr  = (const float*)d_in[2];
    const float* topic = (const float*)d_in[3];
    const float* qemb  = (const float*)d_in[4];
    const float* ne    = (const float*)d_in[5];
    const float* W1    = (const float*)d_in[6];
    const float* b1    = (const float*)d_in[7];
    const float* W2    = (const float*)d_in[8];
    const float* b2    = (const float*)d_in[9];
    float* out = (float*)d_out;
    const int* srcI = ei;
    const int* dstI = ei + EE;

    cudaFuncSetAttribute(node_gemm, cudaFuncAttributeMaxDynamicSharedMemorySize, SMEM_NODE);
    cudaFuncSetAttribute(edge_gemm, cudaFuncAttributeMaxDynamicSharedMemorySize, SMEM_EDGE);

    prep_a<<<NB_PREPA, 256>>>(W1, topic, b2, out, srcI, dstI);
    conv2<<<(EE + 255) / 256, 256>>>(srcI, dstI);
    prep_xp<<<(NN * 32 + 255) / 256, 256>>>(x, ne, topic);
    // 4th launch -> gets the ncu profile
    node_gemm<<<dim3(1024 / BN, (NN + BM - 1) / BM), 256, SMEM_NODE>>>();
    edge_gemm<<<dim3(512 / BN, (EE + BM - 1) / BM), 256, SMEM_EDGE>>>(
        qemb, attr, srcI, dstI, b1, W2, out);
}